// round 2
// baseline (speedup 1.0000x reference)
#include <cuda_runtime.h>
#include <math.h>

#define Bn 16
#define Cn 128
#define Hn 128
#define Wn 128
#define H2n 64
#define W2n 64
#define Ln 4096
#define PB 128            // positions per GEMM CTA
#define NPB (Ln / PB)     // 32 position blocks
#define WROW 132          // padded smem row (floats), 132*4 % 16 == 0

// ---------------- scratch (no allocs allowed) ----------------
__device__ float g_guide[(size_t)Bn * Cn * Ln];          // 32 MB
__device__ float g_lpart[(size_t)Bn * NPB * Cn * 5];     // 1.3 MB
__device__ float g_attn[(size_t)Bn * Cn * 5];

// ---------------- kernel 1: BN -> GELU -> dw conv 7x7 s2 ----------------
__global__ __launch_bounds__(256) void k_guide(
    const float* __restrict__ x,
    const float* __restrict__ bn_g, const float* __restrict__ bn_b,
    const float* __restrict__ bn_m, const float* __restrict__ bn_v,
    const float* __restrict__ dw_w, const float* __restrict__ dw_b)
{
    __shared__ float gs[21][136];
    __shared__ float ws[49];
    const int rblk = blockIdx.x;   // 0..7  (8 output rows each)
    const int c    = blockIdx.y;
    const int b    = blockIdx.z;
    const int tid  = threadIdx.x;

    if (tid < 49) ws[tid] = dw_w[c * 49 + tid];
    const float scale = bn_g[c] * rsqrtf(bn_v[c] + 1e-5f);
    const float shift = bn_b[c] - bn_m[c] * scale;

    const float* xp = x + ((size_t)(b * Cn + c)) * Hn * Wn;
    const int r0 = rblk * 8;
    const int hbase = 2 * r0 - 3;

    for (int idx = tid; idx < 21 * 134; idx += 256) {
        int r = idx / 134, col = idx % 134;
        int hin = hbase + r, win = col - 3;
        float v = 0.f;
        if (hin >= 0 && hin < Hn && win >= 0 && win < Wn) {
            float t = xp[hin * Wn + win] * scale + shift;
            v = 0.5f * t * (1.0f + erff(t * 0.70710678118654752f));  // exact GELU
        }
        gs[r][col] = v;
    }
    __syncthreads();

    const float bias = dw_b[c];
    float* gp = g_guide + ((size_t)(b * Cn + c)) * Ln;
    for (int o = tid; o < 8 * 64; o += 256) {
        int r = o >> 6, w2 = o & 63;
        float acc = bias;
        #pragma unroll
        for (int ky = 0; ky < 7; ky++)
            #pragma unroll
            for (int kx = 0; kx < 7; kx++)
                acc += gs[2 * r + ky][2 * w2 + kx] * ws[ky * 7 + kx];
        gp[(size_t)(r0 + r) * W2n + w2] = acc;
    }
}

// ---------------- shared helpers for GEMM kernels ----------------
// Load token-n panel X[cin][p] (128 x 128) into smem.
__device__ __forceinline__ void load_x(float* Xs, const float* __restrict__ x,
                                       int b, int n, int l0, int tid)
{
    if (n == 0) {
        const float* gp = g_guide + (size_t)b * Cn * Ln + l0;
        for (int idx = tid; idx < Cn * PB; idx += 256) {
            int cin = idx >> 7, p = idx & 127;
            Xs[cin * WROW + p] = gp[(size_t)cin * Ln + p];
        }
    } else {
        const int s1 = (n - 1) >> 1, s2 = (n - 1) & 1;
        for (int idx = tid; idx < Cn * PB; idx += 256) {
            int cin = idx >> 7, p = idx & 127;
            int l = l0 + p;
            int h2 = l >> 6, w2 = l & 63;
            Xs[cin * WROW + p] =
                x[(((size_t)(b * Cn + cin)) * Hn + (2 * h2 + s1)) * Wn + (2 * w2 + s2)];
        }
    }
}

// acc[8][8] = WT(^T) * Xs over 128 inner dim.  WT layout: [cin][cout] padded rows.
__device__ __forceinline__ void gemm8x8(const float* __restrict__ WT,
                                        const float* __restrict__ Xs,
                                        int ty, int tx, float acc[8][8])
{
    #pragma unroll
    for (int i = 0; i < 8; i++)
        #pragma unroll
        for (int j = 0; j < 8; j++) acc[i][j] = 0.f;

    #pragma unroll 4
    for (int kc = 0; kc < 128; kc++) {
        const float4* wr = (const float4*)(WT + kc * WROW + ty * 8);
        const float4* xr = (const float4*)(Xs + kc * WROW + tx * 8);
        float4 w0 = wr[0], w1 = wr[1];
        float4 x0 = xr[0], x1 = xr[1];
        float wv[8] = {w0.x, w0.y, w0.z, w0.w, w1.x, w1.y, w1.z, w1.w};
        float xv[8] = {x0.x, x0.y, x0.z, x0.w, x1.x, x1.y, x1.z, x1.w};
        #pragma unroll
        for (int i = 0; i < 8; i++)
            #pragma unroll
            for (int j = 0; j < 8; j++)
                acc[i][j] = fmaf(wv[i], xv[j], acc[i][j]);
    }
}

// ---------------- kernel 2: q0, k, partial logits ----------------
extern __shared__ float sm_dyn[];

__global__ __launch_bounds__(256, 1) void k_logits(
    const float* __restrict__ x,
    const float* __restrict__ qkv_w, const float* __restrict__ qkv_b)
{
    float* WqT = sm_dyn;
    float* WkT = sm_dyn + Cn * WROW;
    float* Xs  = sm_dyn + 2 * Cn * WROW;

    const int pblk = blockIdx.x, b = blockIdx.y;
    const int tid = threadIdx.x, ty = tid >> 4, tx = tid & 15;
    const int l0 = pblk * PB;

    for (int idx = tid; idx < Cn * Cn; idx += 256) {
        int cin = idx & 127, cout = idx >> 7;
        WqT[cin * WROW + cout] = qkv_w[cout * Cn + cin];
        WkT[cin * WROW + cout] = qkv_w[(128 + cout) * Cn + cin];
    }
    load_x(Xs, x, b, 0, l0, tid);
    __syncthreads();

    float q0[8][8];
    gemm8x8(WqT, Xs, ty, tx, q0);
    float kbv[8];
    #pragma unroll
    for (int i = 0; i < 8; i++) {
        float qb = qkv_b[ty * 8 + i];
        kbv[i] = qkv_b[128 + ty * 8 + i];
        #pragma unroll
        for (int j = 0; j < 8; j++) q0[i][j] += qb;
    }

    for (int n = 0; n < 5; n++) {
        if (n) {
            __syncthreads();
            load_x(Xs, x, b, n, l0, tid);
            __syncthreads();
        }
        float ka[8][8];
        gemm8x8(WkT, Xs, ty, tx, ka);
        #pragma unroll
        for (int i = 0; i < 8; i++) {
            float s = 0.f;
            #pragma unroll
            for (int j = 0; j < 8; j++) s = fmaf(q0[i][j], ka[i][j] + kbv[i], s);
            // reduce across the 16 tx lanes (same half-warp)
            s += __shfl_xor_sync(0xffffffffu, s, 1);
            s += __shfl_xor_sync(0xffffffffu, s, 2);
            s += __shfl_xor_sync(0xffffffffu, s, 4);
            s += __shfl_xor_sync(0xffffffffu, s, 8);
            if (tx == 0)
                g_lpart[(((size_t)b * NPB + pblk) * Cn + (ty * 8 + i)) * 5 + n] = s;
        }
    }
}

// ---------------- kernel 3: reduce partials, scale, softmax ----------------
__global__ __launch_bounds__(256) void k_softmax()
{
    int idx = blockIdx.x * 256 + threadIdx.x;   // (b*Cn + c)
    if (idx >= Bn * Cn) return;
    int b = idx >> 7, c = idx & 127;
    float lg[5] = {0.f, 0.f, 0.f, 0.f, 0.f};
    for (int pb = 0; pb < NPB; pb++) {
        const float* p = g_lpart + (((size_t)b * NPB + pb) * Cn + c) * 5;
        #pragma unroll
        for (int m = 0; m < 5; m++) lg[m] += p[m];
    }
    const float scale = 0.088388347648318447f;  // 1/sqrt(128)
    float mx = -1e30f;
    #pragma unroll
    for (int m = 0; m < 5; m++) { lg[m] *= scale; mx = fmaxf(mx, lg[m]); }
    float sum = 0.f;
    #pragma unroll
    for (int m = 0; m < 5; m++) { lg[m] = expf(lg[m] - mx); sum += lg[m]; }
    float inv = 1.0f / sum;
    #pragma unroll
    for (int m = 0; m < 5; m++) g_attn[(size_t)idx * 5 + m] = lg[m] * inv;
}

// ---------------- kernel 4: v, out0 = attn-weighted, proj ----------------
__global__ __launch_bounds__(256, 1) void k_out(
    const float* __restrict__ x,
    const float* __restrict__ qkv_w, const float* __restrict__ qkv_b,
    const float* __restrict__ proj_w, const float* __restrict__ proj_b,
    float* __restrict__ out)
{
    float* WvT = sm_dyn;
    float* WpT = sm_dyn + Cn * WROW;
    float* Xs  = sm_dyn + 2 * Cn * WROW;
    float* As  = sm_dyn + 3 * Cn * WROW;  // [128][5]

    const int pblk = blockIdx.x, b = blockIdx.y;
    const int tid = threadIdx.x, ty = tid >> 4, tx = tid & 15;
    const int l0 = pblk * PB;

    for (int idx = tid; idx < Cn * Cn; idx += 256) {
        int cin = idx & 127, cout = idx >> 7;
        WvT[cin * WROW + cout] = qkv_w[(256 + cout) * Cn + cin];
        WpT[cin * WROW + cout] = proj_w[cout * Cn + cin];
    }
    for (int idx = tid; idx < Cn * 5; idx += 256)
        As[idx] = g_attn[(size_t)b * Cn * 5 + idx];
    load_x(Xs, x, b, 0, l0, tid);
    __syncthreads();

    float out0[8][8];
    #pragma unroll
    for (int i = 0; i < 8; i++) {
        float vb = qkv_b[256 + ty * 8 + i];   // softmax weights sum to 1
        #pragma unroll
        for (int j = 0; j < 8; j++) out0[i][j] = vb;
    }

    for (int n = 0; n < 5; n++) {
        if (n) {
            __syncthreads();
            load_x(Xs, x, b, n, l0, tid);
            __syncthreads();
        }
        float va[8][8];
        gemm8x8(WvT, Xs, ty, tx, va);
        #pragma unroll
        for (int i = 0; i < 8; i++) {
            float a = As[(ty * 8 + i) * 5 + n];
            #pragma unroll
            for (int j = 0; j < 8; j++) out0[i][j] = fmaf(a, va[i][j], out0[i][j]);
        }
    }

    __syncthreads();   // all X reads done; reuse Xs for out0 staging
    #pragma unroll
    for (int i = 0; i < 8; i++)
        #pragma unroll
        for (int j = 0; j < 8; j++)
            Xs[(ty * 8 + i) * WROW + tx * 8 + j] = out0[i][j];
    __syncthreads();

    float y[8][8];
    gemm8x8(WpT, Xs, ty, tx, y);

    #pragma unroll
    for (int i = 0; i < 8; i++) {
        int dout = ty * 8 + i;
        float pb = proj_b[dout];
        float* op = out + ((size_t)(b * Cn + dout)) * Ln + l0 + tx * 8;
        float4 v0 = make_float4(y[i][0] + pb, y[i][1] + pb, y[i][2] + pb, y[i][3] + pb);
        float4 v1 = make_float4(y[i][4] + pb, y[i][5] + pb, y[i][6] + pb, y[i][7] + pb);
        ((float4*)op)[0] = v0;
        ((float4*)op)[1] = v1;
    }
}

// ---------------- launch ----------------
extern "C" void kernel_launch(void* const* d_in, const int* in_sizes, int n_in,
                              void* d_out, int out_size)
{
    const float* x      = (const float*)d_in[0];
    const float* bn_g   = (const float*)d_in[1];
    const float* bn_b   = (const float*)d_in[2];
    const float* bn_m   = (const float*)d_in[3];
    const float* bn_v   = (const float*)d_in[4];
    const float* dw_w   = (const float*)d_in[5];
    const float* dw_b   = (const float*)d_in[6];
    const float* qkv_w  = (const float*)d_in[7];
    const float* qkv_b  = (const float*)d_in[8];
    const float* proj_w = (const float*)d_in[9];
    const float* proj_b = (const float*)d_in[10];
    float* out = (float*)d_out;

    const int smem2 = 3 * Cn * WROW * (int)sizeof(float);              // 202,752 B
    const int smem4 = smem2 + Cn * 5 * (int)sizeof(float);             // 205,312 B
    cudaFuncSetAttribute(k_logits, cudaFuncAttributeMaxDynamicSharedMemorySize, smem2);
    cudaFuncSetAttribute(k_out,    cudaFuncAttributeMaxDynamicSharedMemorySize, smem4);

    k_guide<<<dim3(8, Cn, Bn), 256>>>(x, bn_g, bn_b, bn_m, bn_v, dw_w, dw_b);
    k_logits<<<dim3(NPB, Bn), 256, smem2>>>(x, qkv_w, qkv_b);
    k_softmax<<<(Bn * Cn + 255) / 256, 256>>>();
    k_out<<<dim3(NPB, Bn), 256, smem4>>>(x, qkv_w, qkv_b, proj_w, proj_b, out);
}